// round 15
// baseline (speedup 1.0000x reference)
#include <cuda_runtime.h>

#define NN 1024
#define CCH 128
#define MAXB 320
#define BCAP 160
#define NCHUNK 16

// ---------------- scratch (device globals; no allocation) ----------------
__device__ int   g_bs[NN], g_be[NN];
__device__ int   g_seg[64], g_segn;
__device__ float g_A  [NN*12];
__device__ float g_kin[NN*CCH];
__device__ float g_q[NN*CCH],  g_k[NN*CCH];
__device__ float g_wt[5*CCH*CCH];   // 0 qw^T, 1 kw^T, 2..4 (out_w@v_w)^T per l
__device__ float g_bc[CCH];         // out_w[0] @ v_b0
__device__ float g_P [NN*8*MAXB];

__device__ __forceinline__ float wredsum(float v){
  #pragma unroll
  for(int o=16;o;o>>=1) v += __shfl_xor_sync(0xffffffffu, v, o);
  return v;
}
__device__ __forceinline__ float wredmax(float v){
  #pragma unroll
  for(int o=16;o;o>>=1) v = fmaxf(v, __shfl_xor_sync(0xffffffffu, v, o));
  return v;
}

#define SH_C0 0.28209479177387814f
#define SH_C1 0.4886025119029199f
#define SH_S15 1.0925484305920792f
#define SH_S5 0.6307831305050401f

// ---------------- fused prep ----------------
__global__ void __launch_bounds__(256) k_pre(const int* __restrict__ words,
                                             const float* __restrict__ qw,
                                             const float* __restrict__ kw,
                                             const float* __restrict__ vw,
                                             const float* __restrict__ ow,
                                             const float* __restrict__ vb0){
  const int b = blockIdx.x;
  const int t = threadIdx.x;
  if(b == 0){
    __shared__ int mono;
    __shared__ int sb[NN];
    if(t==0){ mono = 1; g_segn = 0; }
    __syncthreads();
    for(int tt=t; tt<NN-1; tt+=256)
      if(words[tt] > words[tt+1]) atomicExch(&mono, 0);
    __syncthreads();
    int mn = mono;
    for(int tt=t; tt<NN; tt+=256) sb[tt] = mn ? words[tt] : words[2*tt];
    __syncthreads();
    for(int tt=t; tt<NN; tt+=256){
      int v = sb[tt];
      int lo=0, hi=NN;
      while(lo<hi){ int mid=(lo+hi)>>1; if(sb[mid] <  v) lo=mid+1; else hi=mid; }
      g_bs[tt]=lo;
      if(lo==tt){ int slot = atomicAdd(&g_segn, 1); g_seg[slot]=tt; }
      lo=tt; hi=NN;
      while(lo<hi){ int mid=(lo+hi)>>1; if(sb[mid] <= v) lo=mid+1; else hi=mid; }
      g_be[tt]=lo;
    }
  } else if(b <= 8){
    int base = (b-1)*4096 + t;
    #pragma unroll
    for(int q=0;q<16;q++)
      reinterpret_cast<float4*>(g_kin)[base + q*256] = make_float4(0.f,0.f,0.f,0.f);
  } else if(b == 9){
    #pragma unroll
    for(int q=0;q<12;q++)
      reinterpret_cast<float4*>(g_A)[t + q*256] = make_float4(0.f,0.f,0.f,0.f);
  } else if(b <= 41){
    int idx = b-10;
    int mat  = idx >> 4;
    int tile = idx & 15;
    const float* src = (mat==0)? qw : kw;
    float* dst = g_wt + mat*CCH*CCH;
    int tx=t&31, ty=t>>5;
    int bx=(tile&3)*32, by=(tile>>2)*32;
    __shared__ float s[32][33];
    #pragma unroll
    for(int r=0;r<32;r+=8) s[ty+r][tx] = src[(by+ty+r)*CCH + bx+tx];
    __syncthreads();
    #pragma unroll
    for(int r=0;r<32;r+=8) dst[(bx+ty+r)*CCH + by+tx] = s[tx][ty+r];
  } else {
    int idx = b-42;
    const int kt = idx & 15;
    const int l  = idx >> 4;
    const int k0 = kt*8;
    const int c  = t & 127;
    const int half = t >> 7;
    __shared__ __align__(16) float svw[128][8];
    if(t < 128){
      const float4* vp = reinterpret_cast<const float4*>(vw + (size_t)l*CCH*CCH + c*CCH + k0);
      float4 a = vp[0], bb = vp[1];
      svw[c][0]=a.x; svw[c][1]=a.y; svw[c][2]=a.z; svw[c][3]=a.w;
      svw[c][4]=bb.x; svw[c][5]=bb.y; svw[c][6]=bb.z; svw[c][7]=bb.w;
    }
    __syncthreads();
    const int kbase = half*4;
    const float4* owp = reinterpret_cast<const float4*>(ow + (size_t)l*CCH*CCH + c*CCH);
    const float4* vbp = reinterpret_cast<const float4*>(vb0);
    float acc[4] = {0,0,0,0};
    float accb = 0.0f;
    const bool dob = (l==0 && kt==0 && half==0);
    #pragma unroll 4
    for(int e4=0; e4<32; e4++){
      float4 o4 = owp[e4];
      const float* s0 = &svw[e4*4+0][kbase];
      const float* s1 = &svw[e4*4+1][kbase];
      const float* s2 = &svw[e4*4+2][kbase];
      const float* s3 = &svw[e4*4+3][kbase];
      #pragma unroll
      for(int kk=0;kk<4;kk++)
        acc[kk] += o4.x*s0[kk] + o4.y*s1[kk] + o4.z*s2[kk] + o4.w*s3[kk];
      if(dob){
        float4 b4 = vbp[e4];
        accb += o4.x*b4.x + o4.y*b4.y + o4.z*b4.z + o4.w*b4.w;
      }
    }
    float* dst = g_wt + (size_t)(2+l)*CCH*CCH;
    #pragma unroll
    for(int kk=0;kk<4;kk++) dst[(k0+kbase+kk)*CCH + c] = acc[kk];
    if(dob) g_bc[c] = accb;
  }
}

// ---------------- pairs: kin accumulation + A accumulation ----------------
__global__ void __launch_bounds__(128) k_pair(const float* __restrict__ pos,
                                              const float* __restrict__ xemb){
  const int j0 = blockIdx.x*8;
  const int chunk = blockIdx.y;
  const int t  = threadIdx.x;
  __shared__ __align__(16) float ssh[16][8][12];
  __shared__ float spj[8][3];
  __shared__ int   sbsj[8];
  __shared__ int   sr[2];
  if(t<8){
    spj[t][0]=pos[(j0+t)*3+0]; spj[t][1]=pos[(j0+t)*3+1]; spj[t][2]=pos[(j0+t)*3+2];
    sbsj[t]=g_bs[j0+t];
  }
  if(t==0){
    int u0=g_bs[j0], u1=g_be[j0];
    #pragma unroll
    for(int q=1;q<8;q++){ u0=min(u0,g_bs[j0+q]); u1=max(u1,g_be[j0+q]); }
    sr[0]=u0; sr[1]=u1;
  }
  __syncthreads();
  const int u0=sr[0], un=sr[1]-sr[0];
  const int c0 = u0 + (un*chunk)/NCHUNK;
  const int c1 = u0 + (un*(chunk+1))/NCHUNK;
  const float invN = 1.0f/(float)NN;
  const float w0 = SH_C0*invN;
  const float w1 = SH_C1*invN/3.0f;
  const float wa = SH_S15*invN/5.0f, wb = SH_S5*invN/5.0f, wc = 0.5f*SH_S15*invN/5.0f;
  float acc[8]={0,0,0,0,0,0,0,0};
  for(int ib=c0; ib<c1; ib+=16){
    __syncthreads();
    {
      int ii=t>>3, jt=t&7;
      int i = ib+ii;
      float* sp = &ssh[ii][jt][0];
      bool ok = (i<c1) && (i != j0+jt) && (g_bs[i]==sbsj[jt]);
      if(!ok){
        #pragma unroll
        for(int m=0;m<9;m++) sp[m]=0.0f;
      } else {
        float dx=pos[i*3+0]-spj[jt][0];
        float dy=pos[i*3+1]-spj[jt][1];
        float dz=pos[i*3+2]-spj[jt][2];
        float d = fmaxf(sqrtf(dx*dx+dy*dy+dz*dz), 1e-8f);
        float inv = 1.0f/d;
        float x=dx*inv, y=dy*inv, z=dz*inv;
        sp[0]=w0;
        sp[1]=w1*x; sp[2]=w1*y; sp[3]=w1*z;
        sp[4]=wa*x*z; sp[5]=wa*x*y;
        sp[6]=wb*(y*y-0.5f*(x*x+z*z));
        sp[7]=wa*y*z; sp[8]=wc*(z*z-x*x);
      }
    }
    __syncthreads();
    int lim = min(16, c1-ib);
    for(int e=t; e<lim*9; e+=128){
      int ii=e/9, m=e-ii*9;
      float s = ssh[ii][0][m]+ssh[ii][1][m]+ssh[ii][2][m]+ssh[ii][3][m]
              + ssh[ii][4][m]+ssh[ii][5][m]+ssh[ii][6][m]+ssh[ii][7][m];
      atomicAdd(&g_A[(ib+ii)*12+m], s);
    }
    for(int ii=0; ii<lim; ii++){
      const float* xr = xemb + (size_t)(ib+ii)*9*CCH + t;
      float xv[9];
      #pragma unroll
      for(int m=0;m<9;m++) xv[m]=xr[m*CCH];
      #pragma unroll
      for(int q=0;q<8;q++){
        const float4* shp = reinterpret_cast<const float4*>(&ssh[ii][q][0]);
        float4 a=shp[0], b=shp[1];
        float c8=ssh[ii][q][8];
        acc[q] += a.x*xv[0]+a.y*xv[1]+a.z*xv[2]+a.w*xv[3]
                + b.x*xv[4]+b.y*xv[5]+b.z*xv[6]+b.w*xv[7]+c8*xv[8];
      }
    }
  }
  #pragma unroll
  for(int q=0;q<8;q++) atomicAdd(&g_kin[(j0+q)*CCH+t], acc[q]);
}

// ---------------- q/k projection GEMM: 256 threads, 2 row-halves share staged X ----------------
__global__ void __launch_bounds__(256) k_gemmqk(const float* __restrict__ xemb,
                                                const float* __restrict__ qb,
                                                const float* __restrict__ kb){
  const int r0 = blockIdx.x*8;
  const int t  = threadIdx.x;
  const int c    = t & 127;
  const int half = t >> 7;
  __shared__ __align__(16) float xs[128*8];
  __shared__ float sA[8][12];
  float* Y; int widx; const float* bias;
  if(r0<1024){
    Y=g_q; widx=0; bias=qb;
    for(int e=t; e<96; e+=256){
      int rr=e/12, m=e-rr*12;
      sA[rr][m]=g_A[(r0+rr)*12+m];
    }
    __syncthreads();
    #pragma unroll
    for(int q=0;q<4;q++){
      int rr = half*4 + q;
      const float* xr = xemb + (size_t)(r0+rr)*9*CCH + c;
      float s = 0.0f;
      #pragma unroll
      for(int m=0;m<9;m++) s += sA[rr][m]*xr[m*CCH];
      xs[c*8+rr] = s;
    }
  } else {
    Y=g_k; widx=1; bias=kb;
    int base=r0-1024;
    __syncthreads();
    #pragma unroll
    for(int q=0;q<4;q++){
      int e = t + q*256;
      int rr = e>>7, k = e&127;
      xs[k*8+rr] = g_kin[(base+rr)*CCH + k];
    }
  }
  __syncthreads();
  const int base=(r0<1024)?r0:(r0-1024);
  const float* Wt = g_wt + (size_t)widx*CCH*CCH;
  float bv = bias[c];
  float acc[4];
  #pragma unroll
  for(int q=0;q<4;q++) acc[q]=bv;
  #pragma unroll 4
  for(int k=0;k<128;k++){
    float wv = Wt[k*CCH + c];
    const float4* xp = reinterpret_cast<const float4*>(&xs[k*8]);
    float4 x = xp[half];
    acc[0]+=x.x*wv; acc[1]+=x.y*wv; acc[2]+=x.z*wv; acc[3]+=x.w*wv;
  }
  #pragma unroll
  for(int q=0;q<4;q++) Y[(base+half*4+q)*CCH+c]=acc[q];
}

// ---------------- scores + softmax per (segment, head, quarter) ----------------
__global__ void __launch_bounds__(256) k_score(){
  const int seg = blockIdx.x;
  if(seg >= g_segn) return;
  const int h    = blockIdx.y & 7;
  const int quarter = blockIdx.y >> 3;   // 0..3
  const int s0 = g_seg[seg];
  const int n  = g_be[s0] - s0;
  const int t  = threadIdx.x;
  const int w  = t>>5, lane = t&31;
  __shared__ __align__(16) float kt[BCAP*20];
  for(int idx=t; idx<n*4; idx+=256){
    int j = idx>>2, d4 = idx&3;
    float4 v = *reinterpret_cast<const float4*>(g_k + (size_t)(s0+j)*CCH + h*16 + d4*4);
    *reinterpret_cast<float4*>(&kt[j*20 + d4*4]) = v;
  }
  __syncthreads();
  for(int il = quarter + 4*w; il < n; il += 32){
    const int i = s0 + il;
    const float4* qp = reinterpret_cast<const float4*>(g_q + (size_t)i*CCH + h*16);
    float4 q0=qp[0], q1=qp[1], q2=qp[2], q3=qp[3];
    float sc[5];
    #pragma unroll
    for(int r=0;r<5;r++){
      int jj = lane + 32*r;
      float dot = -1e30f;
      if(jj < n){
        const float4* kp = reinterpret_cast<const float4*>(&kt[jj*20]);
        float4 a=kp[0], b=kp[1], c=kp[2], d=kp[3];
        dot = (q0.x*a.x + q0.y*a.y + q0.z*a.z + q0.w*a.w)
            + (q1.x*b.x + q1.y*b.y + q1.z*b.z + q1.w*b.w)
            + (q2.x*c.x + q2.y*c.y + q2.z*c.z + q2.w*c.w)
            + (q3.x*d.x + q3.y*d.y + q3.z*d.z + q3.w*d.w);
        dot *= 0.25f;
      }
      sc[r] = dot;
    }
    float mx = fmaxf(fmaxf(fmaxf(sc[0],sc[1]),fmaxf(sc[2],sc[3])),sc[4]);
    mx = wredmax(mx);
    float sm = 0.0f;
    #pragma unroll
    for(int r=0;r<5;r++){
      int jj = lane + 32*r;
      sc[r] = (jj<n) ? __expf(sc[r]-mx) : 0.0f;
      sm += sc[r];
    }
    sm = wredsum(sm);
    float inv = 1.0f/sm;
    float* pr = g_P + ((size_t)i*8+h)*MAXB;
    #pragma unroll
    for(int r=0;r<5;r++){
      int jj = lane + 32*r;
      if(jj<n) pr[jj] = sc[r]*inv;
    }
  }
}

// ---------------- fused attention-mix + out-proj + residual + LayerNorm ----------------
// block (i0=8 nodes, mc=3 m's): wv part accumulates 24 rows in registers,
// stages them to smem, then GEMM vs (out_w@v_w)^T, then LN, writing final out.
__global__ void __launch_bounds__(256) k_wvo(const float* __restrict__ xemb,
                                             const float* __restrict__ lng,
                                             const float* __restrict__ lnb,
                                             float* __restrict__ out){
  const int i0 = blockIdx.x*8;
  const int mc = blockIdx.y*3;
  const int t  = threadIdx.x;
  const int c    = t & 127;
  const int half = t >> 7;
  const int wIH  = (t>>5)&3;   // warp within half
  const int lane = t & 31;
  const int h  = c>>4;
  __shared__ float ssp[2][8][8][33];
  __shared__ __align__(16) float xs[CCH*24];   // [k][row], row = it*3+mm
  __shared__ int sbs[8], sbe[8];
  __shared__ int sr[2];
  __shared__ float rs1[2][4][12], rs2[2][4][12];
  __shared__ float smu[24], srs[24];
  if(t<8){ sbs[t]=g_bs[i0+t]; sbe[t]=g_be[i0+t]; }
  __syncthreads();
  if(t==0){
    int u0=sbs[0], u1=sbe[0];
    #pragma unroll
    for(int q=1;q<8;q++){ u0=min(u0,sbs[q]); u1=max(u1,sbe[q]); }
    sr[0]=u0; sr[1]=u1;
  }
  __syncthreads();
  const int u0=sr[0], u1=sr[1];
  float acc[8][3];
  #pragma unroll
  for(int it=0;it<8;it++){ acc[it][0]=0; acc[it][1]=0; acc[it][2]=0; }
  const int barid = 1 + half;
  for(int jt = u0 + half*32; jt < u1; jt += 64){
    asm volatile("bar.sync %0, 128;" :: "r"(barid) : "memory");
    #pragma unroll
    for(int q=0;q<16;q++){
      int e = c + q*128;
      int it = e>>8, hh=(e>>5)&7, jl=e&31;
      int j = jt+jl;
      float p = 0.0f;
      int rel = j - sbs[it];
      if(j<u1 && rel>=0 && j<sbe[it])
        p = g_P[((size_t)(i0+it)*8+hh)*MAXB + rel];
      ssp[half][it][hh][jl]=p;
    }
    asm volatile("bar.sync %0, 128;" :: "r"(barid) : "memory");
    int lim = min(32, u1-jt);
    for(int jl=0; jl<lim; jl++){
      const float* vr = xemb + (size_t)(jt+jl)*9*CCH + mc*CCH + c;
      float v0=vr[0], v1=vr[CCH], v2=vr[2*CCH];
      #pragma unroll
      for(int it=0;it<8;it++){
        float p = ssp[half][it][h][jl];
        acc[it][0]+=p*v0; acc[it][1]+=p*v1; acc[it][2]+=p*v2;
      }
    }
  }
  // combine halves into xs[c*24 + row]
  if(half==1){
    #pragma unroll
    for(int it=0;it<8;it++)
      #pragma unroll
      for(int mm=0;mm<3;mm++)
        xs[c*24 + it*3+mm] = acc[it][mm];
  }
  __syncthreads();
  if(half==0){
    #pragma unroll
    for(int it=0;it<8;it++)
      #pragma unroll
      for(int mm=0;mm<3;mm++)
        xs[c*24 + it*3+mm] += acc[it][mm];
  }
  __syncthreads();
  // ---- GEMM: 12 rows per half. row mm pattern (r%3): 0 -> W0, 1,2 -> W12 ----
  const int lm0  = (mc==0)?0 : ((mc<4)?1:2);   // l of m = mc
  const int lm12 = ((mc+1)<4)?1:2;             // l of m = mc+1 (== l of mc+2)
  const float* W0  = g_wt + (size_t)(2+lm0 )*CCH*CCH;
  const float* W12 = g_wt + (size_t)(2+lm12)*CCH*CCH;
  float acc2[12];
  {
    float bvv = (mc==0)? g_bc[c] : 0.0f;
    #pragma unroll
    for(int r=0;r<12;r++) acc2[r] = (r%3==0)? bvv : 0.0f;
  }
  #pragma unroll 2
  for(int k=0;k<128;k++){
    float w0v  = W0 [k*CCH + c];
    float w12v = W12[k*CCH + c];
    const float4* xp = reinterpret_cast<const float4*>(&xs[k*24 + half*12]);
    float4 x0=xp[0], x1=xp[1], x2=xp[2];
    acc2[0] += x0.x*w0v;  acc2[1] += x0.y*w12v; acc2[2] += x0.z*w12v;
    acc2[3] += x0.w*w0v;  acc2[4] += x1.x*w12v; acc2[5] += x1.y*w12v;
    acc2[6] += x1.z*w0v;  acc2[7] += x1.w*w12v; acc2[8] += x2.x*w12v;
    acc2[9] += x2.y*w0v;  acc2[10]+= x2.z*w12v; acc2[11]+= x2.w*w12v;
  }
  // ---- residual + LN (each half owns its 12 rows) ----
  #pragma unroll
  for(int r=0;r<12;r++){
    int gr = half*12 + r;
    int it = gr/3, mm = gr - it*3;
    int off = (i0+it)*9*CCH + (mc+mm)*CCH;
    float vv = acc2[r] + xemb[off + c];
    acc2[r] = vv;
    float a = vv, b = vv*vv;
    #pragma unroll
    for(int o=16;o;o>>=1){
      a += __shfl_xor_sync(0xffffffffu, a, o);
      b += __shfl_xor_sync(0xffffffffu, b, o);
    }
    if(lane==0){ rs1[half][wIH][r]=a; rs2[half][wIH][r]=b; }
  }
  __syncthreads();
  if(t<24){
    int hh = t/12, r = t - hh*12;
    float a = rs1[hh][0][r]+rs1[hh][1][r]+rs1[hh][2][r]+rs1[hh][3][r];
    float b = rs2[hh][0][r]+rs2[hh][1][r]+rs2[hh][2][r]+rs2[hh][3][r];
    float mu = a*(1.0f/CCH);
    float var = b*(1.0f/CCH) - mu*mu;
    smu[t]=mu; srs[t]=rsqrtf(var + 1e-5f);
  }
  __syncthreads();
  float g0  = lng[lm0 *CCH + c], b0  = lnb[lm0 *CCH + c];
  float g12 = lng[lm12*CCH + c], b12 = lnb[lm12*CCH + c];
  #pragma unroll
  for(int r=0;r<12;r++){
    int gr = half*12 + r;
    int it = gr/3, mm = gr - it*3;
    int off = (i0+it)*9*CCH + (mc+mm)*CCH;
    float g = (mm==0)? g0 : g12;
    float bb= (mm==0)? b0 : b12;
    out[off + c] = (acc2[r]-smu[gr])*srs[gr]*g + bb;
  }
}

// ---------------- launch ----------------
extern "C" void kernel_launch(void* const* d_in, const int* in_sizes, int n_in,
                              void* d_out, int out_size){
  const float* xemb = (const float*)d_in[0];
  const float* pos  = (const float*)d_in[1];
  const float* q_w  = (const float*)d_in[2];
  const float* q_b  = (const float*)d_in[3];
  const float* k_w  = (const float*)d_in[4];
  const float* k_b  = (const float*)d_in[5];
  const float* v_w  = (const float*)d_in[6];
  const float* v_b0 = (const float*)d_in[7];
  const float* out_w= (const float*)d_in[8];
  const float* ln_g = (const float*)d_in[9];
  const float* ln_b = (const float*)d_in[10];
  const int*   batw = (const int*)d_in[11];
  float* out = (float*)d_out;

  k_pre<<<90, 256>>>(batw, q_w, k_w, v_w, out_w, v_b0);
  k_pair<<<dim3(NN/8, NCHUNK), 128>>>(pos, xemb);
  k_gemmqk<<<256, 256>>>(xemb, q_b, k_b);
  k_score<<<dim3(16, 32), 256>>>();
  k_wvo<<<dim3(NN/8, 3), 256>>>(xemb, ln_g, ln_b, out);
}

// round 16
// speedup vs baseline: 1.0306x; 1.0306x over previous
#include <cuda_runtime.h>

#define NN 1024
#define CCH 128
#define MAXB 320
#define BCAP 160
#define NCHUNK 16

// ---------------- scratch (device globals; no allocation) ----------------
__device__ int   g_bs[NN], g_be[NN];
__device__ int   g_seg[64], g_segn;
__device__ float g_A  [NN*12];
__device__ float g_kin[NN*CCH];
__device__ float g_q[NN*CCH],  g_k[NN*CCH];
__device__ float g_wt[5*CCH*CCH];   // 0 qw^T, 1 kw^T, 2..4 (out_w@v_w)^T per l
__device__ float g_bc[CCH];         // out_w[0] @ v_b0
__device__ float g_O1[NN*9*CCH];
__device__ float g_P [NN*8*MAXB];

__device__ __forceinline__ float wredsum(float v){
  #pragma unroll
  for(int o=16;o;o>>=1) v += __shfl_xor_sync(0xffffffffu, v, o);
  return v;
}
__device__ __forceinline__ float wredmax(float v){
  #pragma unroll
  for(int o=16;o;o>>=1) v = fmaxf(v, __shfl_xor_sync(0xffffffffu, v, o));
  return v;
}

#define SH_C0 0.28209479177387814f
#define SH_C1 0.4886025119029199f
#define SH_S15 1.0925484305920792f
#define SH_S5 0.6307831305050401f

// ---------------- fused prep ----------------
__global__ void __launch_bounds__(256) k_pre(const int* __restrict__ words,
                                             const float* __restrict__ qw,
                                             const float* __restrict__ kw,
                                             const float* __restrict__ vw,
                                             const float* __restrict__ ow,
                                             const float* __restrict__ vb0){
  const int b = blockIdx.x;
  const int t = threadIdx.x;
  if(b == 0){
    __shared__ int mono;
    __shared__ int sb[NN];
    if(t==0){ mono = 1; g_segn = 0; }
    __syncthreads();
    for(int tt=t; tt<NN-1; tt+=256)
      if(words[tt] > words[tt+1]) atomicExch(&mono, 0);
    __syncthreads();
    int mn = mono;
    for(int tt=t; tt<NN; tt+=256) sb[tt] = mn ? words[tt] : words[2*tt];
    __syncthreads();
    for(int tt=t; tt<NN; tt+=256){
      int v = sb[tt];
      int lo=0, hi=NN;
      while(lo<hi){ int mid=(lo+hi)>>1; if(sb[mid] <  v) lo=mid+1; else hi=mid; }
      g_bs[tt]=lo;
      if(lo==tt){ int slot = atomicAdd(&g_segn, 1); g_seg[slot]=tt; }
      lo=tt; hi=NN;
      while(lo<hi){ int mid=(lo+hi)>>1; if(sb[mid] <= v) lo=mid+1; else hi=mid; }
      g_be[tt]=lo;
    }
  } else if(b <= 8){
    int base = (b-1)*4096 + t;
    #pragma unroll
    for(int q=0;q<16;q++)
      reinterpret_cast<float4*>(g_kin)[base + q*256] = make_float4(0.f,0.f,0.f,0.f);
  } else if(b == 9){
    #pragma unroll
    for(int q=0;q<12;q++)
      reinterpret_cast<float4*>(g_A)[t + q*256] = make_float4(0.f,0.f,0.f,0.f);
  } else if(b <= 41){
    int idx = b-10;
    int mat  = idx >> 4;
    int tile = idx & 15;
    const float* src = (mat==0)? qw : kw;
    float* dst = g_wt + mat*CCH*CCH;
    int tx=t&31, ty=t>>5;
    int bx=(tile&3)*32, by=(tile>>2)*32;
    __shared__ float s[32][33];
    #pragma unroll
    for(int r=0;r<32;r+=8) s[ty+r][tx] = src[(by+ty+r)*CCH + bx+tx];
    __syncthreads();
    #pragma unroll
    for(int r=0;r<32;r+=8) dst[(bx+ty+r)*CCH + by+tx] = s[tx][ty+r];
  } else {
    int idx = b-42;
    const int kt = idx & 15;
    const int l  = idx >> 4;
    const int k0 = kt*8;
    const int c  = t & 127;
    const int half = t >> 7;
    __shared__ __align__(16) float svw[128][8];
    if(t < 128){
      const float4* vp = reinterpret_cast<const float4*>(vw + (size_t)l*CCH*CCH + c*CCH + k0);
      float4 a = vp[0], bb = vp[1];
      svw[c][0]=a.x; svw[c][1]=a.y; svw[c][2]=a.z; svw[c][3]=a.w;
      svw[c][4]=bb.x; svw[c][5]=bb.y; svw[c][6]=bb.z; svw[c][7]=bb.w;
    }
    __syncthreads();
    const int kbase = half*4;
    const float4* owp = reinterpret_cast<const float4*>(ow + (size_t)l*CCH*CCH + c*CCH);
    const float4* vbp = reinterpret_cast<const float4*>(vb0);
    float acc[4] = {0,0,0,0};
    float accb = 0.0f;
    const bool dob = (l==0 && kt==0 && half==0);
    #pragma unroll 4
    for(int e4=0; e4<32; e4++){
      float4 o4 = owp[e4];
      const float* s0 = &svw[e4*4+0][kbase];
      const float* s1 = &svw[e4*4+1][kbase];
      const float* s2 = &svw[e4*4+2][kbase];
      const float* s3 = &svw[e4*4+3][kbase];
      #pragma unroll
      for(int kk=0;kk<4;kk++)
        acc[kk] += o4.x*s0[kk] + o4.y*s1[kk] + o4.z*s2[kk] + o4.w*s3[kk];
      if(dob){
        float4 b4 = vbp[e4];
        accb += o4.x*b4.x + o4.y*b4.y + o4.z*b4.z + o4.w*b4.w;
      }
    }
    float* dst = g_wt + (size_t)(2+l)*CCH*CCH;
    #pragma unroll
    for(int kk=0;kk<4;kk++) dst[(k0+kbase+kk)*CCH + c] = acc[kk];
    if(dob) g_bc[c] = accb;
  }
}

// ---------------- pairs: kin accumulation + A accumulation ----------------
__global__ void __launch_bounds__(128) k_pair(const float* __restrict__ pos,
                                              const float* __restrict__ xemb){
  const int j0 = blockIdx.x*8;
  const int chunk = blockIdx.y;
  const int t  = threadIdx.x;
  __shared__ __align__(16) float ssh[16][8][12];
  __shared__ float spj[8][3];
  __shared__ int   sbsj[8];
  __shared__ int   sr[2];
  if(t<8){
    spj[t][0]=pos[(j0+t)*3+0]; spj[t][1]=pos[(j0+t)*3+1]; spj[t][2]=pos[(j0+t)*3+2];
    sbsj[t]=g_bs[j0+t];
  }
  if(t==0){
    int u0=g_bs[j0], u1=g_be[j0];
    #pragma unroll
    for(int q=1;q<8;q++){ u0=min(u0,g_bs[j0+q]); u1=max(u1,g_be[j0+q]); }
    sr[0]=u0; sr[1]=u1;
  }
  __syncthreads();
  const int u0=sr[0], un=sr[1]-sr[0];
  const int c0 = u0 + (un*chunk)/NCHUNK;
  const int c1 = u0 + (un*(chunk+1))/NCHUNK;
  const float invN = 1.0f/(float)NN;
  const float w0 = SH_C0*invN;
  const float w1 = SH_C1*invN/3.0f;
  const float wa = SH_S15*invN/5.0f, wb = SH_S5*invN/5.0f, wc = 0.5f*SH_S15*invN/5.0f;
  float acc[8]={0,0,0,0,0,0,0,0};
  for(int ib=c0; ib<c1; ib+=16){
    __syncthreads();
    {
      int ii=t>>3, jt=t&7;
      int i = ib+ii;
      float* sp = &ssh[ii][jt][0];
      bool ok = (i<c1) && (i != j0+jt) && (g_bs[i]==sbsj[jt]);
      if(!ok){
        #pragma unroll
        for(int m=0;m<9;m++) sp[m]=0.0f;
      } else {
        float dx=pos[i*3+0]-spj[jt][0];
        float dy=pos[i*3+1]-spj[jt][1];
        float dz=pos[i*3+2]-spj[jt][2];
        float d = fmaxf(sqrtf(dx*dx+dy*dy+dz*dz), 1e-8f);
        float inv = 1.0f/d;
        float x=dx*inv, y=dy*inv, z=dz*inv;
        sp[0]=w0;
        sp[1]=w1*x; sp[2]=w1*y; sp[3]=w1*z;
        sp[4]=wa*x*z; sp[5]=wa*x*y;
        sp[6]=wb*(y*y-0.5f*(x*x+z*z));
        sp[7]=wa*y*z; sp[8]=wc*(z*z-x*x);
      }
    }
    __syncthreads();
    int lim = min(16, c1-ib);
    for(int e=t; e<lim*9; e+=128){
      int ii=e/9, m=e-ii*9;
      float s = ssh[ii][0][m]+ssh[ii][1][m]+ssh[ii][2][m]+ssh[ii][3][m]
              + ssh[ii][4][m]+ssh[ii][5][m]+ssh[ii][6][m]+ssh[ii][7][m];
      atomicAdd(&g_A[(ib+ii)*12+m], s);
    }
    for(int ii=0; ii<lim; ii++){
      const float* xr = xemb + (size_t)(ib+ii)*9*CCH + t;
      float xv[9];
      #pragma unroll
      for(int m=0;m<9;m++) xv[m]=xr[m*CCH];
      #pragma unroll
      for(int q=0;q<8;q++){
        const float4* shp = reinterpret_cast<const float4*>(&ssh[ii][q][0]);
        float4 a=shp[0], b=shp[1];
        float c8=ssh[ii][q][8];
        acc[q] += a.x*xv[0]+a.y*xv[1]+a.z*xv[2]+a.w*xv[3]
                + b.x*xv[4]+b.y*xv[5]+b.z*xv[6]+b.w*xv[7]+c8*xv[8];
      }
    }
  }
  #pragma unroll
  for(int q=0;q<8;q++) atomicAdd(&g_kin[(j0+q)*CCH+t], acc[q]);
}

// ---------------- q/k projection GEMM: 4 rows/block, 256 threads, halves split rows ----------------
__global__ void __launch_bounds__(256) k_gemmqk(const float* __restrict__ xemb,
                                                const float* __restrict__ qb,
                                                const float* __restrict__ kb){
  const int r0 = blockIdx.x*4;
  const int t  = threadIdx.x;
  const int c    = t & 127;
  const int half = t >> 7;       // 0: rows 0-1, 1: rows 2-3
  __shared__ __align__(16) float xs[128*4];
  __shared__ float sA[4][12];
  float* Y; int widx; const float* bias;
  if(r0<1024){
    Y=g_q; widx=0; bias=qb;
    for(int e=t; e<48; e+=256){
      int rr=e/12, m=e-rr*12;
      sA[rr][m]=g_A[(r0+rr)*12+m];
    }
    __syncthreads();
    #pragma unroll
    for(int q=0;q<2;q++){
      int rr = half*2 + q;
      const float* xr = xemb + (size_t)(r0+rr)*9*CCH + c;
      float s = 0.0f;
      #pragma unroll
      for(int m=0;m<9;m++) s += sA[rr][m]*xr[m*CCH];
      xs[c*4+rr] = s;
    }
  } else {
    Y=g_k; widx=1; bias=kb;
    int base=r0-1024;
    __syncthreads();
    #pragma unroll
    for(int q=0;q<2;q++){
      int e = t + q*256;
      int rr = e>>7, k = e&127;
      xs[k*4+rr] = g_kin[(base+rr)*CCH + k];
    }
  }
  __syncthreads();
  const int base=(r0<1024)?r0:(r0-1024);
  const float* Wt = g_wt + (size_t)widx*CCH*CCH;
  float bv = bias[c];
  float acc0=bv, acc1=bv;
  #pragma unroll 4
  for(int k=0;k<128;k++){
    float wv = Wt[k*CCH + c];
    const float2* xp = reinterpret_cast<const float2*>(&xs[k*4]);
    float2 x = xp[half];
    acc0 += x.x*wv; acc1 += x.y*wv;
  }
  Y[(base+half*2+0)*CCH+c]=acc0;
  Y[(base+half*2+1)*CCH+c]=acc1;
}

// ---------------- scores + softmax per (segment, head, quarter) ----------------
__global__ void __launch_bounds__(256) k_score(){
  const int seg = blockIdx.x;
  if(seg >= g_segn) return;
  const int h    = blockIdx.y & 7;
  const int quarter = blockIdx.y >> 3;   // 0..3
  const int s0 = g_seg[seg];
  const int n  = g_be[s0] - s0;
  const int t  = threadIdx.x;
  const int w  = t>>5, lane = t&31;
  __shared__ __align__(16) float kt[BCAP*20];
  for(int idx=t; idx<n*4; idx+=256){
    int j = idx>>2, d4 = idx&3;
    float4 v = *reinterpret_cast<const float4*>(g_k + (size_t)(s0+j)*CCH + h*16 + d4*4);
    *reinterpret_cast<float4*>(&kt[j*20 + d4*4]) = v;
  }
  __syncthreads();
  for(int il = quarter + 4*w; il < n; il += 32){
    const int i = s0 + il;
    const float4* qp = reinterpret_cast<const float4*>(g_q + (size_t)i*CCH + h*16);
    float4 q0=qp[0], q1=qp[1], q2=qp[2], q3=qp[3];
    float sc[5];
    #pragma unroll
    for(int r=0;r<5;r++){
      int jj = lane + 32*r;
      float dot = -1e30f;
      if(jj < n){
        const float4* kp = reinterpret_cast<const float4*>(&kt[jj*20]);
        float4 a=kp[0], b=kp[1], c=kp[2], d=kp[3];
        dot = (q0.x*a.x + q0.y*a.y + q0.z*a.z + q0.w*a.w)
            + (q1.x*b.x + q1.y*b.y + q1.z*b.z + q1.w*b.w)
            + (q2.x*c.x + q2.y*c.y + q2.z*c.z + q2.w*c.w)
            + (q3.x*d.x + q3.y*d.y + q3.z*d.z + q3.w*d.w);
        dot *= 0.25f;
      }
      sc[r] = dot;
    }
    float mx = fmaxf(fmaxf(fmaxf(sc[0],sc[1]),fmaxf(sc[2],sc[3])),sc[4]);
    mx = wredmax(mx);
    float sm = 0.0f;
    #pragma unroll
    for(int r=0;r<5;r++){
      int jj = lane + 32*r;
      sc[r] = (jj<n) ? __expf(sc[r]-mx) : 0.0f;
      sm += sc[r];
    }
    sm = wredsum(sm);
    float inv = 1.0f/sm;
    float* pr = g_P + ((size_t)i*8+h)*MAXB;
    #pragma unroll
    for(int r=0;r<5;r++){
      int jj = lane + 32*r;
      if(jj<n) pr[jj] = sc[r]*inv;
    }
  }
}

// ---------------- attention mix: 256 threads, halves split j-windows ----------------
__global__ void __launch_bounds__(256) k_wv(const float* __restrict__ xemb){
  const int i0 = blockIdx.x*8;
  const int mc = blockIdx.y*3;
  const int t  = threadIdx.x;
  const int c    = t & 127;
  const int half = t >> 7;
  const int h  = c>>4;
  __shared__ float ssp[2][8][8][33];
  __shared__ float red[8][3][128];
  __shared__ int sbs[8], sbe[8];
  __shared__ int sr[2];
  if(t<8){ sbs[t]=g_bs[i0+t]; sbe[t]=g_be[i0+t]; }
  __syncthreads();
  if(t==0){
    int u0=sbs[0], u1=sbe[0];
    #pragma unroll
    for(int q=1;q<8;q++){ u0=min(u0,sbs[q]); u1=max(u1,sbe[q]); }
    sr[0]=u0; sr[1]=u1;
  }
  __syncthreads();
  const int u0=sr[0], u1=sr[1];
  float acc[8][3];
  #pragma unroll
  for(int it=0;it<8;it++){ acc[it][0]=0; acc[it][1]=0; acc[it][2]=0; }
  const int barid = 1 + half;
  for(int jt = u0 + half*32; jt < u1; jt += 64){
    asm volatile("bar.sync %0, 128;" :: "r"(barid) : "memory");
    #pragma unroll
    for(int q=0;q<16;q++){
      int e = c + q*128;
      int it = e>>8, hh=(e>>5)&7, jl=e&31;
      int j = jt+jl;
      float p = 0.0f;
      int rel = j - sbs[it];
      if(j<u1 && rel>=0 && j<sbe[it])
        p = g_P[((size_t)(i0+it)*8+hh)*MAXB + rel];
      ssp[half][it][hh][jl]=p;
    }
    asm volatile("bar.sync %0, 128;" :: "r"(barid) : "memory");
    int lim = min(32, u1-jt);
    for(int jl=0; jl<lim; jl++){
      const float* vr = xemb + (size_t)(jt+jl)*9*CCH + mc*CCH + c;
      float v0=vr[0], v1=vr[CCH], v2=vr[2*CCH];
      #pragma unroll
      for(int it=0;it<8;it++){
        float p = ssp[half][it][h][jl];
        acc[it][0]+=p*v0; acc[it][1]+=p*v1; acc[it][2]+=p*v2;
      }
    }
  }
  if(half==1){
    #pragma unroll
    for(int it=0;it<8;it++)
      #pragma unroll
      for(int mm=0;mm<3;mm++)
        red[it][mm][c]=acc[it][mm];
  }
  __syncthreads();
  if(half==0){
    #pragma unroll
    for(int it=0;it<8;it++)
      #pragma unroll
      for(int mm=0;mm<3;mm++)
        g_O1[((size_t)(i0+it)*9 + mc+mm)*CCH + c] = acc[it][mm] + red[it][mm][c];
  }
}

// ---------------- combined out-proj GEMM + residual + LayerNorm: 8 rows/block ----------------
__global__ void __launch_bounds__(128) k_gemmo(const float* __restrict__ xemb,
                                               const float* __restrict__ lng,
                                               const float* __restrict__ lnb,
                                               float* __restrict__ out){
  const int r0 = blockIdx.x*8;
  const int t  = threadIdx.x;
  const int w  = t>>5, lane = t&31;
  int l, offs[8];
  bool dobias=false;
  if(r0<1024){
    l=0; dobias=true;
    #pragma unroll
    for(int rr=0;rr<8;rr++) offs[rr]=(r0+rr)*9*CCH;
  } else if(r0<4096){
    l=1;
    int q0=r0-1024;
    #pragma unroll
    for(int rr=0;rr<8;rr++){ int q=q0+rr; offs[rr]=(q/3)*9*CCH + (1+q%3)*CCH; }
  } else {
    l=2;
    int q0=r0-4096;
    #pragma unroll
    for(int rr=0;rr<8;rr++){ int q=q0+rr; offs[rr]=(q/5)*9*CCH + (4+q%5)*CCH; }
  }
  __shared__ __align__(16) float xs[128*8];
  __shared__ int soffs[8];
  if(t<8) soffs[t]=offs[t];
  __syncthreads();
  #pragma unroll
  for(int q=0;q<8;q++){
    int e = t + q*128;
    int rr = e>>7, k = e&127;
    xs[k*8+rr] = g_O1[soffs[rr]+k];
  }
  __syncthreads();
  const float* Wt = g_wt + (size_t)(2+l)*CCH*CCH;
  float bv = dobias ? g_bc[t] : 0.0f;
  float acc[8];
  #pragma unroll
  for(int rr=0;rr<8;rr++) acc[rr]=bv;
  #pragma unroll 4
  for(int k=0;k<128;k++){
    float wv = Wt[k*CCH + t];
    const float4* xp = reinterpret_cast<const float4*>(&xs[k*8]);
    float4 x0=xp[0], x1=xp[1];
    acc[0]+=x0.x*wv; acc[1]+=x0.y*wv; acc[2]+=x0.z*wv; acc[3]+=x0.w*wv;
    acc[4]+=x1.x*wv; acc[5]+=x1.y*wv; acc[6]+=x1.z*wv; acc[7]+=x1.w*wv;
  }
  float v[8];
  #pragma unroll
  for(int rr=0;rr<8;rr++) v[rr] = acc[rr] + xemb[offs[rr]+t];
  float s1[8], s2[8];
  #pragma unroll
  for(int rr=0;rr<8;rr++){
    float a=v[rr], b=v[rr]*v[rr];
    #pragma unroll
    for(int o=16;o;o>>=1){
      a += __shfl_xor_sync(0xffffffffu, a, o);
      b += __shfl_xor_sync(0xffffffffu, b, o);
    }
    s1[rr]=a; s2[rr]=b;
  }
  __shared__ float rs1[4][8], rs2[4][8], smu[8], srs[8];
  if(lane==0){
    #pragma unroll
    for(int rr=0;rr<8;rr++){ rs1[w][rr]=s1[rr]; rs2[w][rr]=s2[rr]; }
  }
  __syncthreads();
  if(t<8){
    float a = rs1[0][t]+rs1[1][t]+rs1[2][t]+rs1[3][t];
    float b = rs2[0][t]+rs2[1][t]+rs2[2][t]+rs2[3][t];
    float mu = a*(1.0f/CCH);
    float var = b*(1.0f/CCH) - mu*mu;
    smu[t]=mu; srs[t]=rsqrtf(var + 1e-5f);
  }
  __syncthreads();
  float gv = lng[l*CCH+t], bb = lnb[l*CCH+t];
  #pragma unroll
  for(int rr=0;rr<8;rr++)
    out[offs[rr]+t] = (v[rr]-smu[rr])*srs[rr]*gv + bb;
}

// ---------------- launch ----------------
extern "C" void kernel_launch(void* const* d_in, const int* in_sizes, int n_in,
                              void* d_out, int out_size){
  const float* xemb = (const float*)d_in[0];
  const float* pos  = (const float*)d_in[1];
  const float* q_w  = (const float*)d_in[2];
  const float* q_b  = (const float*)d_in[3];
  const float* k_w  = (const float*)d_in[4];
  const float* k_b  = (const float*)d_in[5];
  const float* v_w  = (const float*)d_in[6];
  const float* v_b0 = (const float*)d_in[7];
  const float* out_w= (const float*)d_in[8];
  const float* ln_g = (const float*)d_in[9];
  const float* ln_b = (const float*)d_in[10];
  const int*   batw = (const int*)d_in[11];
  float* out = (float*)d_out;

  k_pre<<<90, 256>>>(batw, q_w, k_w, v_w, out_w, v_b0);
  k_pair<<<dim3(NN/8, NCHUNK), 128>>>(pos, xemb);
  k_gemmqk<<<512, 256>>>(xemb, q_b, k_b);
  k_score<<<dim3(16, 32), 256>>>();
  k_wv<<<dim3(NN/8, 3), 256>>>(xemb);
  k_gemmo<<<1152, 128>>>(xemb, ln_g, ln_b, out);
}